// round 3
// baseline (speedup 1.0000x reference)
#include <cuda_runtime.h>

// Problem constants (sizes also derived from in_sizes at launch for safety)
#define NMAX 40000
#define EMAX 640000

// Scratch (device globals: allocation-free per harness rules)
__device__ int   g_deg[NMAX];
__device__ int   g_rowptr[NMAX + 1];
__device__ int   g_cursor[NMAX];
__device__ int   g_col[EMAX];
__device__ float g_dinv[NMAX];
__device__ float g_buf0[(size_t)NMAX * 128];
__device__ float g_buf1[(size_t)NMAX * 128];

// ---------------------------------------------------------------------------
// 0) zero the degree array (memset node on __device__ symbol is NOT
//    graph-capturable -> do it with a kernel)
// ---------------------------------------------------------------------------
__global__ void zero_deg_kernel(int N) {
    int i = blockIdx.x * blockDim.x + threadIdx.x;
    if (i < N) g_deg[i] = 0;
}

// ---------------------------------------------------------------------------
// 1) degree count (edges by dst; self-loops accounted in dinv as deg+1)
//    edge_index is int32 (JAX default x64-disabled downcasts int64 -> int32)
// ---------------------------------------------------------------------------
__global__ void deg_kernel(const int* __restrict__ dst, int E, int N) {
    int i = blockIdx.x * blockDim.x + threadIdx.x;
    if (i < E) {
        int d = dst[i];
        d = max(0, min(d, N - 1));   // defensive clamp
        atomicAdd(&g_deg[d], 1);
    }
}

// ---------------------------------------------------------------------------
// 2) single-block scan: rowptr (exclusive scan of deg), cursor copy, dinv
// ---------------------------------------------------------------------------
__global__ void scan_kernel(int N) {
    __shared__ int sm[1024];
    __shared__ int carry_s;
    int tid = threadIdx.x;
    if (tid == 0) carry_s = 0;
    __syncthreads();
    for (int base = 0; base < N; base += 1024) {
        int i = base + tid;
        int v = (i < N) ? g_deg[i] : 0;
        if (i < N) g_dinv[i] = rsqrtf((float)v + 1.0f);   // +1 = self-loop
        sm[tid] = v;
        __syncthreads();
        #pragma unroll
        for (int off = 1; off < 1024; off <<= 1) {
            int t = (tid >= off) ? sm[tid - off] : 0;
            __syncthreads();
            sm[tid] += t;
            __syncthreads();
        }
        int excl = sm[tid] - v;
        int c = carry_s;
        if (i < N) { g_rowptr[i] = c + excl; g_cursor[i] = c + excl; }
        __syncthreads();
        if (tid == 1023) carry_s = c + sm[1023];
        __syncthreads();
    }
    if (tid == 0) g_rowptr[N] = carry_s;
}

// ---------------------------------------------------------------------------
// 3) CSR fill (counting-sort placement)
// ---------------------------------------------------------------------------
__global__ void fill_kernel(const int* __restrict__ src,
                            const int* __restrict__ dst, int E, int N) {
    int i = blockIdx.x * blockDim.x + threadIdx.x;
    if (i < E) {
        int d = dst[i];
        int s = src[i];
        d = max(0, min(d, N - 1));
        s = max(0, min(s, N - 1));
        int pos = atomicAdd(&g_cursor[d], 1);
        g_col[pos] = s;
    }
}

// ---------------------------------------------------------------------------
// 4) SGEMM: C[M,BN] = A[M,128] @ B[128,BN]   (K fixed = 128)
//    BM=128, BK=16, TM=TN=8
// ---------------------------------------------------------------------------
template <int BN>
__global__ void sgemm_kernel(const float* __restrict__ A,
                             const float* __restrict__ B,
                             float* __restrict__ C, int M) {
    constexpr int BM = 128, BK = 16, TM = 8, TN = 8;
    constexpr int THREADS = (BM / TM) * (BN / TN);
    __shared__ float As[BK][BM + 1];
    __shared__ float Bs[BK][BN];
    int tid = threadIdx.x;
    int tx = tid % (BN / TN);
    int ty = tid / (BN / TN);
    int m0 = blockIdx.x * BM;

    float acc[TM][TN];
    #pragma unroll
    for (int i = 0; i < TM; i++)
        #pragma unroll
        for (int j = 0; j < TN; j++) acc[i][j] = 0.f;

    for (int k0 = 0; k0 < 128; k0 += BK) {
        // A tile -> As (transposed)
        #pragma unroll
        for (int f = tid; f < BM * BK / 4; f += THREADS) {
            int row = f >> 2;
            int kq = f & 3;
            float4 v = make_float4(0.f, 0.f, 0.f, 0.f);
            int gm = m0 + row;
            if (gm < M) v = *(const float4*)(A + (size_t)gm * 128 + k0 + kq * 4);
            As[kq * 4 + 0][row] = v.x;
            As[kq * 4 + 1][row] = v.y;
            As[kq * 4 + 2][row] = v.z;
            As[kq * 4 + 3][row] = v.w;
        }
        // B tile -> Bs
        #pragma unroll
        for (int f = tid; f < BK * BN / 4; f += THREADS) {
            int kk = f / (BN / 4);
            int nq = f % (BN / 4);
            *(float4*)&Bs[kk][nq * 4] =
                *(const float4*)(B + (size_t)(k0 + kk) * BN + nq * 4);
        }
        __syncthreads();
        #pragma unroll
        for (int kk = 0; kk < BK; kk++) {
            float a[TM], b[TN];
            #pragma unroll
            for (int i = 0; i < TM; i++) a[i] = As[kk][ty * TM + i];
            #pragma unroll
            for (int j = 0; j < TN; j++) b[j] = Bs[kk][tx * TN + j];
            #pragma unroll
            for (int i = 0; i < TM; i++)
                #pragma unroll
                for (int j = 0; j < TN; j++) acc[i][j] += a[i] * b[j];
        }
        __syncthreads();
    }
    #pragma unroll
    for (int i = 0; i < TM; i++) {
        int gm = m0 + ty * TM + i;
        if (gm < M) {
            #pragma unroll
            for (int j = 0; j < TN; j += 4)
                *(float4*)(C + (size_t)gm * BN + tx * TN + j) =
                    make_float4(acc[i][j], acc[i][j + 1], acc[i][j + 2], acc[i][j + 3]);
        }
    }
}

// ---------------------------------------------------------------------------
// 5) Aggregation: warp per node, gather h[src]*dinv[src]*dinv[dst], + self,
//    + bias, optional ReLU. D = 128 (float4/lane) or 64 (float2/lane).
// ---------------------------------------------------------------------------
template <int D, bool RELU>
__global__ void agg_kernel(const float* __restrict__ hin,
                           float* __restrict__ hout,
                           const float* __restrict__ bias, int N) {
    constexpr int VEC = D / 32;
    int warp = (blockIdx.x * blockDim.x + threadIdx.x) >> 5;
    int lane = threadIdx.x & 31;
    if (warp >= N) return;

    float dn = g_dinv[warp];
    float acc[VEC];
    {
        float ws = dn * dn;  // self-loop norm
        if constexpr (VEC == 4) {
            float4 v = *(const float4*)(hin + (size_t)warp * D + lane * 4);
            acc[0] = ws * v.x; acc[1] = ws * v.y; acc[2] = ws * v.z; acc[3] = ws * v.w;
        } else {
            float2 v = *(const float2*)(hin + (size_t)warp * D + lane * 2);
            acc[0] = ws * v.x; acc[1] = ws * v.y;
        }
    }
    int e = g_rowptr[warp];
    const int e1 = g_rowptr[warp + 1];
    for (; e + 4 <= e1; e += 4) {
        int s0 = g_col[e], s1 = g_col[e + 1], s2 = g_col[e + 2], s3 = g_col[e + 3];
        float w0 = g_dinv[s0] * dn, w1 = g_dinv[s1] * dn;
        float w2 = g_dinv[s2] * dn, w3 = g_dinv[s3] * dn;
        if constexpr (VEC == 4) {
            float4 v0 = *(const float4*)(hin + (size_t)s0 * D + lane * 4);
            float4 v1 = *(const float4*)(hin + (size_t)s1 * D + lane * 4);
            float4 v2 = *(const float4*)(hin + (size_t)s2 * D + lane * 4);
            float4 v3 = *(const float4*)(hin + (size_t)s3 * D + lane * 4);
            acc[0] += w0 * v0.x + w1 * v1.x + w2 * v2.x + w3 * v3.x;
            acc[1] += w0 * v0.y + w1 * v1.y + w2 * v2.y + w3 * v3.y;
            acc[2] += w0 * v0.z + w1 * v1.z + w2 * v2.z + w3 * v3.z;
            acc[3] += w0 * v0.w + w1 * v1.w + w2 * v2.w + w3 * v3.w;
        } else {
            float2 v0 = *(const float2*)(hin + (size_t)s0 * D + lane * 2);
            float2 v1 = *(const float2*)(hin + (size_t)s1 * D + lane * 2);
            float2 v2 = *(const float2*)(hin + (size_t)s2 * D + lane * 2);
            float2 v3 = *(const float2*)(hin + (size_t)s3 * D + lane * 2);
            acc[0] += w0 * v0.x + w1 * v1.x + w2 * v2.x + w3 * v3.x;
            acc[1] += w0 * v0.y + w1 * v1.y + w2 * v2.y + w3 * v3.y;
        }
    }
    for (; e < e1; e++) {
        int s = g_col[e];
        float w = g_dinv[s] * dn;
        if constexpr (VEC == 4) {
            float4 v = *(const float4*)(hin + (size_t)s * D + lane * 4);
            acc[0] += w * v.x; acc[1] += w * v.y; acc[2] += w * v.z; acc[3] += w * v.w;
        } else {
            float2 v = *(const float2*)(hin + (size_t)s * D + lane * 2);
            acc[0] += w * v.x; acc[1] += w * v.y;
        }
    }
    if constexpr (VEC == 4) {
        float4 b = *(const float4*)(bias + lane * 4);
        float4 o = make_float4(acc[0] + b.x, acc[1] + b.y, acc[2] + b.z, acc[3] + b.w);
        if (RELU) {
            o.x = fmaxf(o.x, 0.f); o.y = fmaxf(o.y, 0.f);
            o.z = fmaxf(o.z, 0.f); o.w = fmaxf(o.w, 0.f);
        }
        *(float4*)(hout + (size_t)warp * D + lane * 4) = o;
    } else {
        float2 b = *(const float2*)(bias + lane * 2);
        float2 o = make_float2(acc[0] + b.x, acc[1] + b.y);
        if (RELU) { o.x = fmaxf(o.x, 0.f); o.y = fmaxf(o.y, 0.f); }
        *(float2*)(hout + (size_t)warp * D + lane * 2) = o;
    }
}

// ---------------------------------------------------------------------------
// 6) final projection: out[N,2] = h[N,64] @ Wout[64,2] + bout
// ---------------------------------------------------------------------------
__global__ void out_proj_kernel(const float* __restrict__ h,
                                const float* __restrict__ Wout,
                                const float* __restrict__ bout,
                                float* __restrict__ out, int N) {
    __shared__ float Ws[128];
    if (threadIdx.x < 128) Ws[threadIdx.x] = Wout[threadIdx.x];
    __syncthreads();
    int r = blockIdx.x * blockDim.x + threadIdx.x;
    if (r >= N) return;
    float a0 = 0.f, a1 = 0.f;
    const float4* hp = (const float4*)(h + (size_t)r * 64);
    #pragma unroll
    for (int j = 0; j < 16; j++) {
        float4 v = hp[j];
        a0 += v.x * Ws[(j * 4 + 0) * 2] + v.y * Ws[(j * 4 + 1) * 2] +
              v.z * Ws[(j * 4 + 2) * 2] + v.w * Ws[(j * 4 + 3) * 2];
        a1 += v.x * Ws[(j * 4 + 0) * 2 + 1] + v.y * Ws[(j * 4 + 1) * 2 + 1] +
              v.z * Ws[(j * 4 + 2) * 2 + 1] + v.w * Ws[(j * 4 + 3) * 2 + 1];
    }
    out[(size_t)r * 2 + 0] = a0 + bout[0];
    out[(size_t)r * 2 + 1] = a1 + bout[1];
}

// ---------------------------------------------------------------------------
extern "C" void kernel_launch(void* const* d_in, const int* in_sizes, int n_in,
                              void* d_out, int out_size) {
    (void)n_in; (void)out_size;
    const float* x    = (const float*)d_in[0];
    const int*   ei   = (const int*)d_in[1];   // int32! (JAX default x64 off)
    const float* W1   = (const float*)d_in[2];
    const float* b1   = (const float*)d_in[3];
    const float* W2   = (const float*)d_in[4];
    const float* b2   = (const float*)d_in[5];
    const float* W3   = (const float*)d_in[6];
    const float* b3   = (const float*)d_in[7];
    const float* Wout = (const float*)d_in[8];
    const float* bout = (const float*)d_in[9];

    int N = in_sizes[0] / 128;
    int E = in_sizes[1] / 2;

    float* out  = (float*)d_out;
    float* hout = out + (size_t)N * 2;   // tuple layout: out[N,2] then h[N,64]

    float* buf0; cudaGetSymbolAddress((void**)&buf0, g_buf0);
    float* buf1; cudaGetSymbolAddress((void**)&buf1, g_buf1);

    const int* src = ei;
    const int* dst = ei + E;

    // Graph normalization + CSR build (cheap, re-done per replay)
    zero_deg_kernel<<<(N + 255) / 256, 256>>>(N);
    deg_kernel<<<(E + 255) / 256, 256>>>(dst, E, N);
    scan_kernel<<<1, 1024>>>(N);
    fill_kernel<<<(E + 255) / 256, 256>>>(src, dst, E, N);

    int gM = (N + 127) / 128;
    int gW = (N * 32 + 255) / 256;   // warp-per-node grids

    // Layer 1: h = relu(Agg(x @ W1) + b1)
    sgemm_kernel<128><<<gM, 256>>>(x, W1, buf0, N);
    agg_kernel<128, true><<<gW, 256>>>(buf0, buf1, b1, N);
    // Layer 2
    sgemm_kernel<128><<<gM, 256>>>(buf1, W2, buf0, N);
    agg_kernel<128, true><<<gW, 256>>>(buf0, buf1, b2, N);
    // Layer 3 (embedding, no relu) -> h region of d_out
    sgemm_kernel<64><<<gM, 128>>>(buf1, W3, buf0, N);
    agg_kernel<64, false><<<gW, 256>>>(buf0, hout, b3, N);
    // Output head
    out_proj_kernel<<<(N + 127) / 128, 128>>>(hout, Wout, bout, out, N);
}

// round 4
// speedup vs baseline: 1.3875x; 1.3875x over previous
#include <cuda_runtime.h>

#define NMAX 40000
#define EMAX 640000

// Scratch (device globals: allocation-free per harness rules)
__device__ int   g_deg[NMAX];
__device__ int   g_rowptr[NMAX + 1];
__device__ int   g_cursor[NMAX];
__device__ int   g_col[EMAX];
__device__ float g_dinv[NMAX];
__device__ int   g_bsum[64];
__device__ float g_buf0[(size_t)NMAX * 128];
__device__ float g_buf1[(size_t)NMAX * 128];

// ---------------------------------------------------------------------------
// 0) zero degree array (memset node on __device__ symbol not capturable)
// ---------------------------------------------------------------------------
__global__ void zero_deg_kernel(int N) {
    int i = blockIdx.x * blockDim.x + threadIdx.x;
    if (i < N) g_deg[i] = 0;
}

// ---------------------------------------------------------------------------
// 1) degree count (edges by dst)
// ---------------------------------------------------------------------------
__global__ void deg_kernel(const int* __restrict__ dst, int E, int N) {
    int i = blockIdx.x * blockDim.x + threadIdx.x;
    if (i < E) {
        int d = dst[i];
        d = max(0, min(d, N - 1));
        atomicAdd(&g_deg[d], 1);
    }
}

// ---------------------------------------------------------------------------
// 2) hierarchical exclusive scan of g_deg -> g_rowptr/g_cursor (+ dinv)
//    scan1: per-1024-chunk sums; scan2: serial scan of <=64 sums;
//    scan3: per-chunk scan + offset
// ---------------------------------------------------------------------------
__global__ void scan1_kernel(int N) {
    __shared__ int sh[256];
    int t = threadIdx.x;
    int base = blockIdx.x * 1024 + t * 4;
    int s = 0;
    #pragma unroll
    for (int i = 0; i < 4; i++) if (base + i < N) s += g_deg[base + i];
    sh[t] = s;
    __syncthreads();
    #pragma unroll
    for (int off = 128; off > 0; off >>= 1) {
        if (t < off) sh[t] += sh[t + off];
        __syncthreads();
    }
    if (t == 0) g_bsum[blockIdx.x] = sh[0];
}

__global__ void scan2_kernel(int nb, int N) {
    if (threadIdx.x == 0) {
        int run = 0;
        for (int i = 0; i < nb; i++) { int v = g_bsum[i]; g_bsum[i] = run; run += v; }
        g_rowptr[N] = run;   // == E
    }
}

__global__ void scan3_kernel(int N) {
    __shared__ int sh[256];
    int t = threadIdx.x;
    int base = blockIdx.x * 1024 + t * 4;
    int v[4];
    int s = 0;
    #pragma unroll
    for (int i = 0; i < 4; i++) {
        v[i] = (base + i < N) ? g_deg[base + i] : 0;
        s += v[i];
    }
    sh[t] = s;
    __syncthreads();
    #pragma unroll
    for (int off = 1; off < 256; off <<= 1) {
        int x = (t >= off) ? sh[t - off] : 0;
        __syncthreads();
        sh[t] += x;
        __syncthreads();
    }
    int run = g_bsum[blockIdx.x] + sh[t] - s;   // exclusive offset for this thread
    #pragma unroll
    for (int i = 0; i < 4; i++) {
        int idx = base + i;
        if (idx < N) {
            g_rowptr[idx] = run;
            g_cursor[idx] = run;
            g_dinv[idx]   = rsqrtf((float)v[i] + 1.0f);   // +1 = self-loop
            run += v[i];
        }
    }
}

// ---------------------------------------------------------------------------
// 3) CSR fill (counting-sort placement)
// ---------------------------------------------------------------------------
__global__ void fill_kernel(const int* __restrict__ src,
                            const int* __restrict__ dst, int E, int N) {
    int i = blockIdx.x * blockDim.x + threadIdx.x;
    if (i < E) {
        int d = max(0, min(dst[i], N - 1));
        int s = max(0, min(src[i], N - 1));
        int pos = atomicAdd(&g_cursor[d], 1);
        g_col[pos] = s;
    }
}

// ---------------------------------------------------------------------------
// 4) Tensor-core GEMM: C[M,BN] = A[M,128] @ B[128,BN], 3xTF32 path
//    (hi*hi + hi*lo + lo*hi; error ~2^-22 relative)
//    8 warps/block: warp_m = wid>>1 (32 rows), warp_n = wid&1 (BN/2 cols)
//    No smem: fragments straight from L1 (B is 64KB, fully cached).
// ---------------------------------------------------------------------------
__device__ __forceinline__ unsigned f2tf32(float f) {
    unsigned u;
    asm("cvt.rna.tf32.f32 %0, %1;" : "=r"(u) : "f"(f));
    return u;
}
__device__ __forceinline__ void split_tf32(float f, unsigned& hi, unsigned& lo) {
    hi = f2tf32(f);
    lo = f2tf32(f - __uint_as_float(hi));
}
__device__ __forceinline__ void mma_tf32(float* c, const unsigned* a, const unsigned* b) {
    asm volatile(
        "mma.sync.aligned.m16n8k8.row.col.f32.tf32.tf32.f32 "
        "{%0,%1,%2,%3}, {%4,%5,%6,%7}, {%8,%9}, {%0,%1,%2,%3};\n"
        : "+f"(c[0]), "+f"(c[1]), "+f"(c[2]), "+f"(c[3])
        : "r"(a[0]), "r"(a[1]), "r"(a[2]), "r"(a[3]), "r"(b[0]), "r"(b[1]));
}

template <int BN>
__global__ void __launch_bounds__(256, 1)
mma_gemm_kernel(const float* __restrict__ A,
                const float* __restrict__ B,
                float* __restrict__ C, int M) {
    constexpr int NT = BN / 16;          // n-tiles (8 cols each) per warp
    int tid = threadIdx.x;
    int wid = tid >> 5, lane = tid & 31;
    int warp_m = wid >> 1, warp_n = wid & 1;
    int grp = lane >> 2, qid = lane & 3;
    int m0 = blockIdx.x * 128 + warp_m * 32;
    int col0 = warp_n * (BN / 2);

    float acc[2][NT][4];
    #pragma unroll
    for (int mt = 0; mt < 2; mt++)
        #pragma unroll
        for (int nt = 0; nt < NT; nt++)
            #pragma unroll
            for (int j = 0; j < 4; j++) acc[mt][nt][j] = 0.f;

    for (int k0 = 0; k0 < 128; k0 += 8) {
        unsigned ahi[2][4], alo[2][4];
        #pragma unroll
        for (int mt = 0; mt < 2; mt++) {
            int r0 = m0 + mt * 16 + grp;
            int r1 = r0 + 8;
            int rc0 = min(r0, M - 1), rc1 = min(r1, M - 1);
            float f0 = A[(size_t)rc0 * 128 + k0 + qid];
            float f1 = A[(size_t)rc1 * 128 + k0 + qid];
            float f2 = A[(size_t)rc0 * 128 + k0 + qid + 4];
            float f3 = A[(size_t)rc1 * 128 + k0 + qid + 4];
            split_tf32(f0, ahi[mt][0], alo[mt][0]);
            split_tf32(f1, ahi[mt][1], alo[mt][1]);
            split_tf32(f2, ahi[mt][2], alo[mt][2]);
            split_tf32(f3, ahi[mt][3], alo[mt][3]);
        }
        unsigned bhi[NT][2], blo[NT][2];
        #pragma unroll
        for (int nt = 0; nt < NT; nt++) {
            int c = col0 + nt * 8 + grp;
            float g0 = B[(size_t)(k0 + qid) * BN + c];
            float g1 = B[(size_t)(k0 + qid + 4) * BN + c];
            split_tf32(g0, bhi[nt][0], blo[nt][0]);
            split_tf32(g1, bhi[nt][1], blo[nt][1]);
        }
        #pragma unroll
        for (int mt = 0; mt < 2; mt++)
            #pragma unroll
            for (int nt = 0; nt < NT; nt++) {
                mma_tf32(acc[mt][nt], ahi[mt], bhi[nt]);
                mma_tf32(acc[mt][nt], ahi[mt], blo[nt]);
                mma_tf32(acc[mt][nt], alo[mt], bhi[nt]);
            }
    }
    #pragma unroll
    for (int mt = 0; mt < 2; mt++) {
        int r0 = m0 + mt * 16 + grp;
        int r1 = r0 + 8;
        #pragma unroll
        for (int nt = 0; nt < NT; nt++) {
            int c = col0 + nt * 8 + qid * 2;
            if (r0 < M) {
                C[(size_t)r0 * BN + c]     = acc[mt][nt][0];
                C[(size_t)r0 * BN + c + 1] = acc[mt][nt][1];
            }
            if (r1 < M) {
                C[(size_t)r1 * BN + c]     = acc[mt][nt][2];
                C[(size_t)r1 * BN + c + 1] = acc[mt][nt][3];
            }
        }
    }
}

// ---------------------------------------------------------------------------
// 5) Aggregation: warp per node, CSR gather, + self-loop, + bias, opt ReLU
// ---------------------------------------------------------------------------
template <int D, bool RELU>
__global__ void agg_kernel(const float* __restrict__ hin,
                           float* __restrict__ hout,
                           const float* __restrict__ bias, int N) {
    constexpr int VEC = D / 32;
    int warp = (blockIdx.x * blockDim.x + threadIdx.x) >> 5;
    int lane = threadIdx.x & 31;
    if (warp >= N) return;

    float dn = g_dinv[warp];
    float acc[VEC];
    {
        float ws = dn * dn;
        if constexpr (VEC == 4) {
            float4 v = *(const float4*)(hin + (size_t)warp * D + lane * 4);
            acc[0] = ws * v.x; acc[1] = ws * v.y; acc[2] = ws * v.z; acc[3] = ws * v.w;
        } else {
            float2 v = *(const float2*)(hin + (size_t)warp * D + lane * 2);
            acc[0] = ws * v.x; acc[1] = ws * v.y;
        }
    }
    int e = g_rowptr[warp];
    const int e1 = g_rowptr[warp + 1];
    for (; e + 4 <= e1; e += 4) {
        int s0 = g_col[e], s1 = g_col[e + 1], s2 = g_col[e + 2], s3 = g_col[e + 3];
        float w0 = g_dinv[s0] * dn, w1 = g_dinv[s1] * dn;
        float w2 = g_dinv[s2] * dn, w3 = g_dinv[s3] * dn;
        if constexpr (VEC == 4) {
            float4 v0 = *(const float4*)(hin + (size_t)s0 * D + lane * 4);
            float4 v1 = *(const float4*)(hin + (size_t)s1 * D + lane * 4);
            float4 v2 = *(const float4*)(hin + (size_t)s2 * D + lane * 4);
            float4 v3 = *(const float4*)(hin + (size_t)s3 * D + lane * 4);
            acc[0] += w0 * v0.x + w1 * v1.x + w2 * v2.x + w3 * v3.x;
            acc[1] += w0 * v0.y + w1 * v1.y + w2 * v2.y + w3 * v3.y;
            acc[2] += w0 * v0.z + w1 * v1.z + w2 * v2.z + w3 * v3.z;
            acc[3] += w0 * v0.w + w1 * v1.w + w2 * v2.w + w3 * v3.w;
        } else {
            float2 v0 = *(const float2*)(hin + (size_t)s0 * D + lane * 2);
            float2 v1 = *(const float2*)(hin + (size_t)s1 * D + lane * 2);
            float2 v2 = *(const float2*)(hin + (size_t)s2 * D + lane * 2);
            float2 v3 = *(const float2*)(hin + (size_t)s3 * D + lane * 2);
            acc[0] += w0 * v0.x + w1 * v1.x + w2 * v2.x + w3 * v3.x;
            acc[1] += w0 * v0.y + w1 * v1.y + w2 * v2.y + w3 * v3.y;
        }
    }
    for (; e < e1; e++) {
        int s = g_col[e];
        float w = g_dinv[s] * dn;
        if constexpr (VEC == 4) {
            float4 v = *(const float4*)(hin + (size_t)s * D + lane * 4);
            acc[0] += w * v.x; acc[1] += w * v.y; acc[2] += w * v.z; acc[3] += w * v.w;
        } else {
            float2 v = *(const float2*)(hin + (size_t)s * D + lane * 2);
            acc[0] += w * v.x; acc[1] += w * v.y;
        }
    }
    if constexpr (VEC == 4) {
        float4 b = *(const float4*)(bias + lane * 4);
        float4 o = make_float4(acc[0] + b.x, acc[1] + b.y, acc[2] + b.z, acc[3] + b.w);
        if (RELU) {
            o.x = fmaxf(o.x, 0.f); o.y = fmaxf(o.y, 0.f);
            o.z = fmaxf(o.z, 0.f); o.w = fmaxf(o.w, 0.f);
        }
        *(float4*)(hout + (size_t)warp * D + lane * 4) = o;
    } else {
        float2 b = *(const float2*)(bias + lane * 2);
        float2 o = make_float2(acc[0] + b.x, acc[1] + b.y);
        if (RELU) { o.x = fmaxf(o.x, 0.f); o.y = fmaxf(o.y, 0.f); }
        *(float2*)(hout + (size_t)warp * D + lane * 2) = o;
    }
}

// ---------------------------------------------------------------------------
// 6) final projection: out[N,2] = h[N,64] @ Wout[64,2] + bout
// ---------------------------------------------------------------------------
__global__ void out_proj_kernel(const float* __restrict__ h,
                                const float* __restrict__ Wout,
                                const float* __restrict__ bout,
                                float* __restrict__ out, int N) {
    __shared__ float Ws[128];
    if (threadIdx.x < 128) Ws[threadIdx.x] = Wout[threadIdx.x];
    __syncthreads();
    int r = blockIdx.x * blockDim.x + threadIdx.x;
    if (r >= N) return;
    float a0 = 0.f, a1 = 0.f;
    const float4* hp = (const float4*)(h + (size_t)r * 64);
    #pragma unroll
    for (int j = 0; j < 16; j++) {
        float4 v = hp[j];
        a0 += v.x * Ws[(j * 4 + 0) * 2] + v.y * Ws[(j * 4 + 1) * 2] +
              v.z * Ws[(j * 4 + 2) * 2] + v.w * Ws[(j * 4 + 3) * 2];
        a1 += v.x * Ws[(j * 4 + 0) * 2 + 1] + v.y * Ws[(j * 4 + 1) * 2 + 1] +
              v.z * Ws[(j * 4 + 2) * 2 + 1] + v.w * Ws[(j * 4 + 3) * 2 + 1];
    }
    out[(size_t)r * 2 + 0] = a0 + bout[0];
    out[(size_t)r * 2 + 1] = a1 + bout[1];
}

// ---------------------------------------------------------------------------
extern "C" void kernel_launch(void* const* d_in, const int* in_sizes, int n_in,
                              void* d_out, int out_size) {
    (void)n_in; (void)out_size;
    const float* x    = (const float*)d_in[0];
    const int*   ei   = (const int*)d_in[1];   // int32 (JAX default x64 off)
    const float* W1   = (const float*)d_in[2];
    const float* b1   = (const float*)d_in[3];
    const float* W2   = (const float*)d_in[4];
    const float* b2   = (const float*)d_in[5];
    const float* W3   = (const float*)d_in[6];
    const float* b3   = (const float*)d_in[7];
    const float* Wout = (const float*)d_in[8];
    const float* bout = (const float*)d_in[9];

    int N = in_sizes[0] / 128;
    int E = in_sizes[1] / 2;

    float* out  = (float*)d_out;
    float* hout = out + (size_t)N * 2;   // tuple layout: out[N,2] then h[N,64]

    float* buf0; cudaGetSymbolAddress((void**)&buf0, g_buf0);
    float* buf1; cudaGetSymbolAddress((void**)&buf1, g_buf1);

    const int* src = ei;
    const int* dst = ei + E;

    // CSR build (re-done per replay; deterministic)
    int nb = (N + 1023) / 1024;
    zero_deg_kernel<<<(N + 255) / 256, 256>>>(N);
    deg_kernel<<<(E + 255) / 256, 256>>>(dst, E, N);
    scan1_kernel<<<nb, 256>>>(N);
    scan2_kernel<<<1, 32>>>(nb, N);
    scan3_kernel<<<nb, 256>>>(N);
    fill_kernel<<<(E + 255) / 256, 256>>>(src, dst, E, N);

    int gM = (N + 127) / 128;
    int gW = (N * 32 + 255) / 256;

    // Layer 1: h = relu(Agg(x @ W1) + b1)
    mma_gemm_kernel<128><<<gM, 256>>>(x, W1, buf0, N);
    agg_kernel<128, true><<<gW, 256>>>(buf0, buf1, b1, N);
    // Layer 2
    mma_gemm_kernel<128><<<gM, 256>>>(buf1, W2, buf0, N);
    agg_kernel<128, true><<<gW, 256>>>(buf0, buf1, b2, N);
    // Layer 3 (embedding, no relu) -> h region of d_out
    mma_gemm_kernel<64><<<gM, 256>>>(buf1, W3, buf0, N);
    agg_kernel<64, false><<<gW, 256>>>(buf0, hout, b3, N);
    // Output head
    out_proj_kernel<<<(N + 127) / 128, 128>>>(hout, Wout, bout, out, N);
}

// round 5
// speedup vs baseline: 1.4381x; 1.0365x over previous
#include <cuda_runtime.h>

#define NMAX 40000
#define EMAX 640000

// Scratch (device globals: allocation-free per harness rules)
__device__ int   g_deg[NMAX];
__device__ int   g_rowptr[NMAX + 1];
__device__ int   g_cursor[NMAX];
__device__ int   g_col[EMAX];
__device__ float g_dinv[NMAX];
__device__ int   g_bsum[64];
__device__ float g_buf0[(size_t)NMAX * 128];
__device__ float g_buf1[(size_t)NMAX * 128];
// Pre-split fragment-ordered weights: [kt][c][qid] -> {hi(k0+qid,c), lo, hi(k0+qid+4,c), lo}
__device__ float4 g_pb1[16 * 128 * 4];
__device__ float4 g_pb2[16 * 128 * 4];
__device__ float4 g_pb3[16 * 64 * 4];

// ---------------------------------------------------------------------------
__device__ __forceinline__ float trunc13(float f) {
    return __uint_as_float(__float_as_uint(f) & 0xffffe000u);
}

// ---------------------------------------------------------------------------
// 0) zero degree array
// ---------------------------------------------------------------------------
__global__ void zero_deg_kernel(int N) {
    int i = blockIdx.x * blockDim.x + threadIdx.x;
    if (i < N) g_deg[i] = 0;
}

// ---------------------------------------------------------------------------
// 1) degree count (edges by dst)
// ---------------------------------------------------------------------------
__global__ void deg_kernel(const int* __restrict__ dst, int E, int N) {
    int i = blockIdx.x * blockDim.x + threadIdx.x;
    if (i < E) {
        int d = dst[i];
        d = max(0, min(d, N - 1));
        atomicAdd(&g_deg[d], 1);
    }
}

// ---------------------------------------------------------------------------
// 2) hierarchical exclusive scan -> rowptr/cursor + dinv
// ---------------------------------------------------------------------------
__global__ void scan1_kernel(int N) {
    __shared__ int sh[256];
    int t = threadIdx.x;
    int base = blockIdx.x * 1024 + t * 4;
    int s = 0;
    #pragma unroll
    for (int i = 0; i < 4; i++) if (base + i < N) s += g_deg[base + i];
    sh[t] = s;
    __syncthreads();
    #pragma unroll
    for (int off = 128; off > 0; off >>= 1) {
        if (t < off) sh[t] += sh[t + off];
        __syncthreads();
    }
    if (t == 0) g_bsum[blockIdx.x] = sh[0];
}

__global__ void scan2_kernel(int nb, int N) {
    if (threadIdx.x == 0) {
        int run = 0;
        for (int i = 0; i < nb; i++) { int v = g_bsum[i]; g_bsum[i] = run; run += v; }
        g_rowptr[N] = run;
    }
}

__global__ void scan3_kernel(int N) {
    __shared__ int sh[256];
    int t = threadIdx.x;
    int base = blockIdx.x * 1024 + t * 4;
    int v[4];
    int s = 0;
    #pragma unroll
    for (int i = 0; i < 4; i++) {
        v[i] = (base + i < N) ? g_deg[base + i] : 0;
        s += v[i];
    }
    sh[t] = s;
    __syncthreads();
    #pragma unroll
    for (int off = 1; off < 256; off <<= 1) {
        int x = (t >= off) ? sh[t - off] : 0;
        __syncthreads();
        sh[t] += x;
        __syncthreads();
    }
    int run = g_bsum[blockIdx.x] + sh[t] - s;
    #pragma unroll
    for (int i = 0; i < 4; i++) {
        int idx = base + i;
        if (idx < N) {
            g_rowptr[idx] = run;
            g_cursor[idx] = run;
            g_dinv[idx]   = rsqrtf((float)v[i] + 1.0f);
            run += v[i];
        }
    }
}

// ---------------------------------------------------------------------------
// 3) CSR fill
// ---------------------------------------------------------------------------
__global__ void fill_kernel(const int* __restrict__ src,
                            const int* __restrict__ dst, int E, int N) {
    int i = blockIdx.x * blockDim.x + threadIdx.x;
    if (i < E) {
        int d = max(0, min(dst[i], N - 1));
        int s = max(0, min(src[i], N - 1));
        int pos = atomicAdd(&g_cursor[d], 1);
        g_col[pos] = s;
    }
}

// ---------------------------------------------------------------------------
// 3b) pack weights into fragment-ordered split form (once per launch, cheap)
//     entry i = ((kt*BN)+c)*4 + qid  -> {hi,lo of W[kt*8+qid][c], W[kt*8+qid+4][c]}
// ---------------------------------------------------------------------------
__global__ void pack_w_kernel(const float* __restrict__ W, float4* __restrict__ PB, int BN) {
    int i = blockIdx.x * blockDim.x + threadIdx.x;
    int total = 16 * BN * 4;
    if (i >= total) return;
    int qid = i & 3;
    int c   = (i >> 2) % BN;
    int kt  = (i >> 2) / BN;
    float f0 = W[(kt * 8 + qid) * BN + c];
    float f1 = W[(kt * 8 + qid + 4) * BN + c];
    float4 v;
    v.x = trunc13(f0); v.y = f0 - v.x;
    v.z = trunc13(f1); v.w = f1 - v.z;
    PB[i] = v;
}

// ---------------------------------------------------------------------------
// 4) Tensor-core GEMM, 3xTF32 (hi*hi + hi*lo + lo*hi), pre-split B fragments
// ---------------------------------------------------------------------------
__device__ __forceinline__ void mma_tf32(float* c, const unsigned* a, const unsigned* b) {
    asm volatile(
        "mma.sync.aligned.m16n8k8.row.col.f32.tf32.tf32.f32 "
        "{%0,%1,%2,%3}, {%4,%5,%6,%7}, {%8,%9}, {%0,%1,%2,%3};\n"
        : "+f"(c[0]), "+f"(c[1]), "+f"(c[2]), "+f"(c[3])
        : "r"(a[0]), "r"(a[1]), "r"(a[2]), "r"(a[3]), "r"(b[0]), "r"(b[1]));
}

template <int BN>
__global__ void __launch_bounds__(256, 1)
mma_gemm_kernel(const float* __restrict__ A,
                const float4* __restrict__ PB,
                float* __restrict__ C, int M) {
    constexpr int NT = BN / 16;
    int tid = threadIdx.x;
    int wid = tid >> 5, lane = tid & 31;
    int warp_m = wid >> 1, warp_n = wid & 1;
    int grp = lane >> 2, qid = lane & 3;
    int m0 = blockIdx.x * 128 + warp_m * 32;
    int col0 = warp_n * (BN / 2);

    float acc[2][NT][4];
    #pragma unroll
    for (int mt = 0; mt < 2; mt++)
        #pragma unroll
        for (int nt = 0; nt < NT; nt++)
            #pragma unroll
            for (int j = 0; j < 4; j++) acc[mt][nt][j] = 0.f;

    #pragma unroll 2
    for (int kt = 0; kt < 16; kt++) {
        int k0 = kt * 8;
        unsigned ahi[2][4], alo[2][4];
        #pragma unroll
        for (int mt = 0; mt < 2; mt++) {
            int r0 = m0 + mt * 16 + grp;
            int r1 = r0 + 8;
            int rc0 = min(r0, M - 1), rc1 = min(r1, M - 1);
            float f0 = A[(size_t)rc0 * 128 + k0 + qid];
            float f1 = A[(size_t)rc1 * 128 + k0 + qid];
            float f2 = A[(size_t)rc0 * 128 + k0 + qid + 4];
            float f3 = A[(size_t)rc1 * 128 + k0 + qid + 4];
            float h0 = trunc13(f0), h1 = trunc13(f1), h2 = trunc13(f2), h3 = trunc13(f3);
            ahi[mt][0] = __float_as_uint(h0); alo[mt][0] = __float_as_uint(f0 - h0);
            ahi[mt][1] = __float_as_uint(h1); alo[mt][1] = __float_as_uint(f1 - h1);
            ahi[mt][2] = __float_as_uint(h2); alo[mt][2] = __float_as_uint(f2 - h2);
            ahi[mt][3] = __float_as_uint(h3); alo[mt][3] = __float_as_uint(f3 - h3);
        }
        #pragma unroll
        for (int nt = 0; nt < NT; nt++) {
            int c = col0 + nt * 8 + grp;
            float4 pb = PB[((kt * BN) + c) * 4 + qid];
            unsigned bh[2] = { __float_as_uint(pb.x), __float_as_uint(pb.z) };
            unsigned bl[2] = { __float_as_uint(pb.y), __float_as_uint(pb.w) };
            #pragma unroll
            for (int mt = 0; mt < 2; mt++) {
                mma_tf32(acc[mt][nt], ahi[mt], bh);
                mma_tf32(acc[mt][nt], ahi[mt], bl);
                mma_tf32(acc[mt][nt], alo[mt], bh);
            }
        }
    }
    #pragma unroll
    for (int mt = 0; mt < 2; mt++) {
        int r0 = m0 + mt * 16 + grp;
        int r1 = r0 + 8;
        #pragma unroll
        for (int nt = 0; nt < NT; nt++) {
            int c = col0 + nt * 8 + qid * 2;
            if (r0 < M) {
                C[(size_t)r0 * BN + c]     = acc[mt][nt][0];
                C[(size_t)r0 * BN + c + 1] = acc[mt][nt][1];
            }
            if (r1 < M) {
                C[(size_t)r1 * BN + c]     = acc[mt][nt][2];
                C[(size_t)r1 * BN + c + 1] = acc[mt][nt][3];
            }
        }
    }
}

// ---------------------------------------------------------------------------
// 5) Aggregation D=128: warp per node, CSR gather, + self, + bias, ReLU
// ---------------------------------------------------------------------------
template <bool RELU>
__global__ void agg128_kernel(const float* __restrict__ hin,
                              float* __restrict__ hout,
                              const float* __restrict__ bias, int N) {
    int warp = (blockIdx.x * blockDim.x + threadIdx.x) >> 5;
    int lane = threadIdx.x & 31;
    if (warp >= N) return;

    float dn = g_dinv[warp];
    float acc[4];
    {
        float ws = dn * dn;
        float4 v = *(const float4*)(hin + (size_t)warp * 128 + lane * 4);
        acc[0] = ws * v.x; acc[1] = ws * v.y; acc[2] = ws * v.z; acc[3] = ws * v.w;
    }
    int e = g_rowptr[warp];
    const int e1 = g_rowptr[warp + 1];
    for (; e + 4 <= e1; e += 4) {
        int s0 = g_col[e], s1 = g_col[e + 1], s2 = g_col[e + 2], s3 = g_col[e + 3];
        float w0 = g_dinv[s0] * dn, w1 = g_dinv[s1] * dn;
        float w2 = g_dinv[s2] * dn, w3 = g_dinv[s3] * dn;
        float4 v0 = *(const float4*)(hin + (size_t)s0 * 128 + lane * 4);
        float4 v1 = *(const float4*)(hin + (size_t)s1 * 128 + lane * 4);
        float4 v2 = *(const float4*)(hin + (size_t)s2 * 128 + lane * 4);
        float4 v3 = *(const float4*)(hin + (size_t)s3 * 128 + lane * 4);
        acc[0] += w0 * v0.x + w1 * v1.x + w2 * v2.x + w3 * v3.x;
        acc[1] += w0 * v0.y + w1 * v1.y + w2 * v2.y + w3 * v3.y;
        acc[2] += w0 * v0.z + w1 * v1.z + w2 * v2.z + w3 * v3.z;
        acc[3] += w0 * v0.w + w1 * v1.w + w2 * v2.w + w3 * v3.w;
    }
    for (; e < e1; e++) {
        int s = g_col[e];
        float w = g_dinv[s] * dn;
        float4 v = *(const float4*)(hin + (size_t)s * 128 + lane * 4);
        acc[0] += w * v.x; acc[1] += w * v.y; acc[2] += w * v.z; acc[3] += w * v.w;
    }
    float4 b = *(const float4*)(bias + lane * 4);
    float4 o = make_float4(acc[0] + b.x, acc[1] + b.y, acc[2] + b.z, acc[3] + b.w);
    if (RELU) {
        o.x = fmaxf(o.x, 0.f); o.y = fmaxf(o.y, 0.f);
        o.z = fmaxf(o.z, 0.f); o.w = fmaxf(o.w, 0.f);
    }
    *(float4*)(hout + (size_t)warp * 128 + lane * 4) = o;
}

// ---------------------------------------------------------------------------
// 5b) Aggregation D=64 with fused output head:
//     h = Agg(emb) + b3 (no relu); out = h @ Wout[64,2] + bout
// ---------------------------------------------------------------------------
__global__ void agg64_out_kernel(const float* __restrict__ hin,
                                 float* __restrict__ hout,
                                 const float* __restrict__ bias,
                                 const float* __restrict__ Wout,
                                 const float* __restrict__ bout,
                                 float* __restrict__ out, int N) {
    int warp = (blockIdx.x * blockDim.x + threadIdx.x) >> 5;
    int lane = threadIdx.x & 31;
    if (warp >= N) return;

    float dn = g_dinv[warp];
    float a0, a1;
    {
        float ws = dn * dn;
        float2 v = *(const float2*)(hin + (size_t)warp * 64 + lane * 2);
        a0 = ws * v.x; a1 = ws * v.y;
    }
    int e = g_rowptr[warp];
    const int e1 = g_rowptr[warp + 1];
    for (; e + 4 <= e1; e += 4) {
        int s0 = g_col[e], s1 = g_col[e + 1], s2 = g_col[e + 2], s3 = g_col[e + 3];
        float w0 = g_dinv[s0] * dn, w1 = g_dinv[s1] * dn;
        float w2 = g_dinv[s2] * dn, w3 = g_dinv[s3] * dn;
        float2 v0 = *(const float2*)(hin + (size_t)s0 * 64 + lane * 2);
        float2 v1 = *(const float2*)(hin + (size_t)s1 * 64 + lane * 2);
        float2 v2 = *(const float2*)(hin + (size_t)s2 * 64 + lane * 2);
        float2 v3 = *(const float2*)(hin + (size_t)s3 * 64 + lane * 2);
        a0 += w0 * v0.x + w1 * v1.x + w2 * v2.x + w3 * v3.x;
        a1 += w0 * v0.y + w1 * v1.y + w2 * v2.y + w3 * v3.y;
    }
    for (; e < e1; e++) {
        int s = g_col[e];
        float w = g_dinv[s] * dn;
        float2 v = *(const float2*)(hin + (size_t)s * 64 + lane * 2);
        a0 += w * v.x; a1 += w * v.y;
    }
    float2 b = *(const float2*)(bias + lane * 2);
    float2 o = make_float2(a0 + b.x, a1 + b.y);
    *(float2*)(hout + (size_t)warp * 64 + lane * 2) = o;

    // fused head: out[warp][j] = sum_c h[c]*Wout[c][j] + bout[j]
    int c0 = lane * 2;
    float p0 = o.x * __ldg(&Wout[c0 * 2])     + o.y * __ldg(&Wout[(c0 + 1) * 2]);
    float p1 = o.x * __ldg(&Wout[c0 * 2 + 1]) + o.y * __ldg(&Wout[(c0 + 1) * 2 + 1]);
    #pragma unroll
    for (int off = 16; off > 0; off >>= 1) {
        p0 += __shfl_xor_sync(0xffffffffu, p0, off);
        p1 += __shfl_xor_sync(0xffffffffu, p1, off);
    }
    if (lane == 0) {
        out[(size_t)warp * 2 + 0] = p0 + __ldg(&bout[0]);
        out[(size_t)warp * 2 + 1] = p1 + __ldg(&bout[1]);
    }
}

// ---------------------------------------------------------------------------
extern "C" void kernel_launch(void* const* d_in, const int* in_sizes, int n_in,
                              void* d_out, int out_size) {
    (void)n_in; (void)out_size;
    const float* x    = (const float*)d_in[0];
    const int*   ei   = (const int*)d_in[1];   // int32 (JAX default x64 off)
    const float* W1   = (const float*)d_in[2];
    const float* b1   = (const float*)d_in[3];
    const float* W2   = (const float*)d_in[4];
    const float* b2   = (const float*)d_in[5];
    const float* W3   = (const float*)d_in[6];
    const float* b3   = (const float*)d_in[7];
    const float* Wout = (const float*)d_in[8];
    const float* bout = (const float*)d_in[9];

    int N = in_sizes[0] / 128;
    int E = in_sizes[1] / 2;

    float* out  = (float*)d_out;
    float* hout = out + (size_t)N * 2;   // tuple layout: out[N,2] then h[N,64]

    float* buf0; cudaGetSymbolAddress((void**)&buf0, g_buf0);
    float* buf1; cudaGetSymbolAddress((void**)&buf1, g_buf1);
    float4* pb1; cudaGetSymbolAddress((void**)&pb1, g_pb1);
    float4* pb2; cudaGetSymbolAddress((void**)&pb2, g_pb2);
    float4* pb3; cudaGetSymbolAddress((void**)&pb3, g_pb3);

    const int* src = ei;
    const int* dst = ei + E;

    // weight pre-split (fragment order)
    pack_w_kernel<<<(16 * 128 * 4 + 255) / 256, 256>>>(W1, pb1, 128);
    pack_w_kernel<<<(16 * 128 * 4 + 255) / 256, 256>>>(W2, pb2, 128);
    pack_w_kernel<<<(16 * 64 * 4 + 255) / 256, 256>>>(W3, pb3, 64);

    // CSR build
    int nb = (N + 1023) / 1024;
    zero_deg_kernel<<<(N + 255) / 256, 256>>>(N);
    deg_kernel<<<(E + 255) / 256, 256>>>(dst, E, N);
    scan1_kernel<<<nb, 256>>>(N);
    scan2_kernel<<<1, 32>>>(nb, N);
    scan3_kernel<<<nb, 256>>>(N);
    fill_kernel<<<(E + 255) / 256, 256>>>(src, dst, E, N);

    int gM = (N + 127) / 128;
    int gW = (N * 32 + 255) / 256;

    // Layer 1
    mma_gemm_kernel<128><<<gM, 256>>>(x, pb1, buf0, N);
    agg128_kernel<true><<<gW, 256>>>(buf0, buf1, b1, N);
    // Layer 2
    mma_gemm_kernel<128><<<gM, 256>>>(buf1, pb2, buf0, N);
    agg128_kernel<true><<<gW, 256>>>(buf0, buf1, b2, N);
    // Layer 3 + fused output head
    mma_gemm_kernel<64><<<gM, 256>>>(buf1, pb3, buf0, N);
    agg64_out_kernel<<<gW, 256>>>(buf0, hout, b3, Wout, bout, out, N);
}